// round 7
// baseline (speedup 1.0000x reference)
#include <cuda_runtime.h>
#include <cuda_fp16.h>
#include <math.h>
#include <stdint.h>

#define N_TOK 4096
#define E_DIM 1024
#define H_DIM 2730
#define HPH   2736          // fp16 weight row pad (×2B = 5472, 16B-aligned)
#define HP2   2752          // g_h fp16 row pad / GEMM2 K extent (43*64)
#define KP2   2752
#define NEXP  8
#define NPAIR 8192
#define MAXT  71            // 8192/128 + 7
#define KC    64

// ---------------- device scratch ----------------
__device__ int   g_cnt[NEXP];
__device__ int   g_off[NEXP + 1];
__device__ int   g_cur[NEXP];
__device__ int   g_te[N_TOK * 2];
__device__ float g_tw[N_TOK * 2];
__device__ int   g_tok[NPAIR];
__device__ float g_wt[NPAIR];
__device__ int   g_tile_e[MAXT];
__device__ int   g_tile_r[MAXT];
__device__ int   g_ntiles;
__device__ __align__(16) __half d_wvh[(size_t)NEXP * E_DIM * HPH + 64];
__device__ __align__(16) __half d_wgh[(size_t)NEXP * E_DIM * HPH + 64];
__device__ __align__(16) __half d_woh[(size_t)NEXP * KP2 * E_DIM];
__device__ __align__(16) __half d_xh[(size_t)N_TOK * E_DIM];
__device__ __align__(16) __half d_gh[(size_t)NPAIR * HP2];
__device__ __align__(16) float  g_acc[(size_t)N_TOK * E_DIM];

// ---------------- PTX helpers ----------------
__device__ __forceinline__ uint32_t smem_u32(const void* p) {
    uint32_t a;
    asm("{ .reg .u64 t; cvta.to.shared.u64 t, %1; cvt.u32.u64 %0, t; }" : "=r"(a) : "l"(p));
    return a;
}
__device__ __forceinline__ void cpa16(uint32_t dst, const void* src) {
    asm volatile("cp.async.cg.shared.global [%0], [%1], 16;" :: "r"(dst), "l"(src) : "memory");
}
#define CPA_COMMIT() asm volatile("cp.async.commit_group;" ::: "memory")
template <int N> __device__ __forceinline__ void cpa_wait() {
    asm volatile("cp.async.wait_group %0;" :: "n"(N) : "memory");
}
#define LDM4(r, a)                                                              \
    asm volatile("ldmatrix.sync.aligned.m8n8.x4.shared.b16 {%0,%1,%2,%3}, [%4];" \
        : "=r"((r)[0]), "=r"((r)[1]), "=r"((r)[2]), "=r"((r)[3]) : "r"(a))
#define LDM4T(r, a)                                                             \
    asm volatile("ldmatrix.sync.aligned.m8n8.x4.trans.shared.b16 {%0,%1,%2,%3}, [%4];" \
        : "=r"((r)[0]), "=r"((r)[1]), "=r"((r)[2]), "=r"((r)[3]) : "r"(a))

__device__ __forceinline__ void mma16(float d[4], const uint32_t a[4], uint32_t b0, uint32_t b1) {
    asm volatile(
        "mma.sync.aligned.m16n8k16.row.col.f32.f16.f16.f32 "
        "{%0,%1,%2,%3}, {%4,%5,%6,%7}, {%8,%9}, {%0,%1,%2,%3};"
        : "+f"(d[0]), "+f"(d[1]), "+f"(d[2]), "+f"(d[3])
        : "r"(a[0]), "r"(a[1]), "r"(a[2]), "r"(a[3]), "r"(b0), "r"(b1));
}

// ---------------- weight conversion ----------------
__global__ void k_cvt_vg(const float* __restrict__ Wv, const float* __restrict__ Wg) {
    size_t p = (size_t)blockIdx.x * blockDim.x + threadIdx.x;
    if (p >= (size_t)NEXP * E_DIM * (HPH / 2)) return;
    int n2 = (int)(p % (HPH / 2));
    size_t r = p / (HPH / 2);
    int n = n2 * 2;
    size_t src = r * H_DIM + n;
    float v0 = (n     < H_DIM) ? Wv[src]     : 0.f;
    float v1 = (n + 1 < H_DIM) ? Wv[src + 1] : 0.f;
    float q0 = (n     < H_DIM) ? Wg[src]     : 0.f;
    float q1 = (n + 1 < H_DIM) ? Wg[src + 1] : 0.f;
    ((__half2*)d_wvh)[r * (HPH / 2) + n2] = __floats2half2_rn(v0, v1);
    ((__half2*)d_wgh)[r * (HPH / 2) + n2] = __floats2half2_rn(q0, q1);
}

__global__ void k_cvt_o(const float* __restrict__ Wo) {
    size_t p = (size_t)blockIdx.x * blockDim.x + threadIdx.x;
    if (p >= (size_t)NEXP * KP2 * (E_DIM / 2)) return;
    int n2 = (int)(p & (E_DIM / 2 - 1));
    size_t r = p >> 9;
    int k = (int)(r % KP2);
    int e = (int)(r / KP2);
    int n = n2 * 2;
    float v0 = 0.f, v1 = 0.f;
    if (k < H_DIM) {
        size_t src = ((size_t)e * H_DIM + k) * E_DIM + n;
        v0 = Wo[src]; v1 = Wo[src + 1];
    }
    ((__half2*)d_woh)[r * (E_DIM / 2) + n2] = __floats2half2_rn(v0, v1);
}

// ---------------- init ----------------
__global__ void k_init(const float* __restrict__ x) {
    int i = blockIdx.x * blockDim.x + threadIdx.x;
    if (i < NEXP) g_cnt[i] = 0;
    float4 v = ((const float4*)x)[i];
    ((float4*)g_acc)[i] = v;
    ((__half2*)d_xh)[2 * i]     = __floats2half2_rn(v.x, v.y);
    ((__half2*)d_xh)[2 * i + 1] = __floats2half2_rn(v.z, v.w);
}

// ---------------- router ----------------
__global__ void k_router(const float* __restrict__ x, const float* __restrict__ Wr) {
    int warp = (blockIdx.x * blockDim.x + threadIdx.x) >> 5;
    int lane = threadIdx.x & 31;
    if (warp >= N_TOK) return;
    const float* xr = x + (size_t)warp * E_DIM;
    float acc[NEXP];
#pragma unroll
    for (int c = 0; c < NEXP; c++) acc[c] = 0.f;
    for (int k = lane; k < E_DIM; k += 32) {
        float xv = xr[k];
#pragma unroll
        for (int c = 0; c < NEXP; c++) acc[c] += xv * Wr[c * E_DIM + k];
    }
#pragma unroll
    for (int c = 0; c < NEXP; c++)
#pragma unroll
        for (int o = 16; o > 0; o >>= 1) acc[c] += __shfl_xor_sync(0xffffffffu, acc[c], o);
    if (lane == 0) {
        int b0 = 0; float v0 = acc[0];
#pragma unroll
        for (int c = 1; c < NEXP; c++) if (acc[c] > v0) { v0 = acc[c]; b0 = c; }
        int b1 = -1; float v1 = -3.4e38f;
#pragma unroll
        for (int c = 0; c < NEXP; c++) if (c != b0 && acc[c] > v1) { v1 = acc[c]; b1 = c; }
        float t = expf(v1 - v0);
        float w0 = 1.f / (1.f + t);
        g_te[warp * 2 + 0] = b0; g_tw[warp * 2 + 0] = w0;
        g_te[warp * 2 + 1] = b1; g_tw[warp * 2 + 1] = t * w0;
        atomicAdd(&g_cnt[b0], 1);
        atomicAdd(&g_cnt[b1], 1);
    }
}

// ---------------- prefix + scatter ----------------
__global__ void k_scatter_one() {
    int t = threadIdx.x;
    if (t == 0) {
        int s = 0;
        for (int c = 0; c < NEXP; c++) { g_off[c] = s; g_cur[c] = s; s += g_cnt[c]; }
        g_off[NEXP] = s;
        int tt = 0;
        for (int c = 0; c < NEXP; c++)
            for (int r = g_off[c]; r < g_off[c + 1]; r += 128) {
                g_tile_e[tt] = c; g_tile_r[tt] = r; tt++;
            }
        g_ntiles = tt;
    }
    __syncthreads();
    for (int n = t; n < N_TOK; n += blockDim.x) {
#pragma unroll
        for (int k = 0; k < 2; k++) {
            int e = g_te[n * 2 + k];
            int slot = atomicAdd(&g_cur[e], 1);
            g_tok[slot] = n;
            g_wt[slot]  = g_tw[n * 2 + k];
        }
    }
}

// ============ GEMM1: fp16 mma, h = silu(X@Wv+bv)*(X@Wg+bg) ============
// CTA 128 tok x 64 H-cols; warps 0-3 -> V, 4-7 -> G (shared A).
// warp tile 64 tok x 32 cols. 3-stage cp.async pipeline, wait_group 1.
#define ST1   36864
#define SM1   (512 + 3 * ST1)
#define ST2   (18432 + 17408)
#define SM2   (3 * ST2)

__global__ void __launch_bounds__(256, 2) k_gemm1(
    const float* __restrict__ bv, const float* __restrict__ bg)
{
    int tile = blockIdx.x;
    if (tile >= g_ntiles) return;
    int e = g_tile_e[tile];
    int rbase = g_tile_r[tile];
    int rend  = g_off[e + 1];
    int cbase = blockIdx.y * 64;

    extern __shared__ __align__(16) char dsm[];
    int* stok = (int*)dsm;
    uint32_t st0 = smem_u32(dsm + 512);
    int t = threadIdx.x, w = t >> 5, l = t & 31;

    if (t < 128) {
        int s = rbase + t;
        stok[t] = g_tok[s < rend ? s : rend - 1];
    }
    __syncthreads();

    const __half* wvp = d_wvh + ((size_t)e * E_DIM) * HPH + cbase;
    const __half* wgp = d_wgh + ((size_t)e * E_DIM) * HPH + cbase;

    auto fill = [&](int c) {
        uint32_t sb = st0 + (c % 3) * ST1;
        int kb = c * KC;
#pragma unroll
        for (int i = 0; i < 4; i++) {          // A: 128 rows x 8 x 16B
            int ch = t + i * 256;
            int row = ch >> 3, cc = ch & 7;
            cpa16(sb + row * 144 + cc * 16, d_xh + (size_t)stok[row] * E_DIM + kb + cc * 8);
        }
#pragma unroll
        for (int i = 0; i < 2; i++) {          // Bv,Bg: 64 k-rows x 8 x 16B each
            int ch = t + i * 256;
            int kr = ch >> 3, cc = ch & 7;
            uint32_t off = kr * 144 + cc * 16;
            cpa16(sb + 18432 + off, wvp + (size_t)(kb + kr) * HPH + cc * 8);
            cpa16(sb + 27648 + off, wgp + (size_t)(kb + kr) * HPH + cc * 8);
        }
    };

    float acc[4][4][4];
#pragma unroll
    for (int mi = 0; mi < 4; mi++)
#pragma unroll
        for (int nt = 0; nt < 4; nt++)
#pragma unroll
            for (int q = 0; q < 4; q++) acc[mi][nt][q] = 0.f;

    int wl = w & 3;
    int wm = wl & 1, wn = wl >> 1;
    bool isG = (w >= 4);
    int g = l >> 3, lr = l & 7;
    uint32_t frag_off = ((g & 1) * 8 + lr) * 144 + (g >> 1) * 16;

    fill(0); CPA_COMMIT();
    fill(1); CPA_COMMIT();
    for (int c = 0; c < 16; c++) {
        if (c + 1 < 16) cpa_wait<1>(); else cpa_wait<0>();
        __syncthreads();
        if (c + 2 < 16) { fill(c + 2); CPA_COMMIT(); }
        uint32_t sb = st0 + (c % 3) * ST1;
        uint32_t aB = sb + wm * 64 * 144;
        uint32_t bB = sb + (isG ? 27648u : 18432u) + wn * 64;
#pragma unroll
        for (int ks = 0; ks < 4; ks++) {
            uint32_t af[4][4], bf[2][4];
#pragma unroll
            for (int mi = 0; mi < 4; mi++)
                LDM4(af[mi], aB + mi * 16 * 144 + ks * 32 + frag_off);
            LDM4T(bf[0], bB + ks * 16 * 144 + frag_off);
            LDM4T(bf[1], bB + ks * 16 * 144 + 32 + frag_off);
#pragma unroll
            for (int mi = 0; mi < 4; mi++) {
                mma16(acc[mi][0], af[mi], bf[0][0], bf[0][1]);
                mma16(acc[mi][1], af[mi], bf[0][2], bf[0][3]);
                mma16(acc[mi][2], af[mi], bf[1][0], bf[1][1]);
                mma16(acc[mi][3], af[mi], bf[1][2], bf[1][3]);
            }
        }
    }

    // epilogue: V warps stage to sV (overlay stage buffers); G warps fuse SwiGLU
    __syncthreads();
    float* sV = (float*)(dsm + 512);
    if (!isG) {
#pragma unroll
        for (int mi = 0; mi < 4; mi++)
#pragma unroll
            for (int nt = 0; nt < 4; nt++) {
                int r0 = wm * 64 + mi * 16 + (l >> 2);
                int c0 = wn * 32 + nt * 8 + (l & 3) * 2;
                *(float2*)&sV[r0 * 66 + c0]       = make_float2(acc[mi][nt][0], acc[mi][nt][1]);
                *(float2*)&sV[(r0 + 8) * 66 + c0] = make_float2(acc[mi][nt][2], acc[mi][nt][3]);
            }
    }
    __syncthreads();
    if (isG) {
        const float* bvB = bv + (size_t)e * H_DIM;
        const float* bgB = bg + (size_t)e * H_DIM;
#pragma unroll
        for (int mi = 0; mi < 4; mi++)
#pragma unroll
            for (int nt = 0; nt < 4; nt++) {
                int r0 = wm * 64 + mi * 16 + (l >> 2);
                int c0 = wn * 32 + nt * 8 + (l & 3) * 2;
#pragma unroll
                for (int h8 = 0; h8 < 2; h8++) {
                    int row = r0 + h8 * 8;
                    int slot = rbase + row;
                    if (slot < rend) {
                        float2 vv = *(float2*)&sV[row * 66 + c0];
                        int gc = cbase + c0;
                        float o0 = 0.f, o1 = 0.f;
                        if (gc < H_DIM) {
                            float a = vv.x + bvB[gc];
                            float gg = acc[mi][nt][h8 * 2] + bgB[gc];
                            o0 = a / (1.f + __expf(-a)) * gg;
                        }
                        if (gc + 1 < H_DIM) {
                            float a = vv.y + bvB[gc + 1];
                            float gg = acc[mi][nt][h8 * 2 + 1] + bgB[gc + 1];
                            o1 = a / (1.f + __expf(-a)) * gg;
                        }
                        *(__half2*)&d_gh[(size_t)slot * HP2 + gc] = __floats2half2_rn(o0, o1);
                    }
                }
            }
    }
}

// ============ GEMM2: acc += w * (h @ Wo + bo), fp16 mma ============
// CTA 128 tok x 128 E-cols; warps 2(M) x 4(N), warp tile 64x32.
// 3-stage cp.async pipeline, wait_group 1.
__global__ void __launch_bounds__(256, 2) k_gemm2(const float* __restrict__ bo)
{
    int tile = blockIdx.x;
    if (tile >= g_ntiles) return;
    int e = g_tile_e[tile];
    int rbase = g_tile_r[tile];
    int rend  = g_off[e + 1];
    int cbase = blockIdx.y * 128;

    extern __shared__ __align__(16) char dsm[];
    uint32_t st0 = smem_u32(dsm);
    int t = threadIdx.x, w = t >> 5, l = t & 31;

    const __half* wop = d_woh + (size_t)e * KP2 * E_DIM + cbase;

    auto fill = [&](int c) {
        uint32_t sb = st0 + (c % 3) * ST2;
        int kb = c * KC;
#pragma unroll
        for (int i = 0; i < 4; i++) {          // A: 128 rows x 8 x 16B
            int ch = t + i * 256;
            int row = ch >> 3, cc = ch & 7;
            int slot = rbase + row; if (slot >= rend) slot = rend - 1;
            cpa16(sb + row * 144 + cc * 16, d_gh + (size_t)slot * HP2 + kb + cc * 8);
        }
#pragma unroll
        for (int i = 0; i < 4; i++) {          // B: 64 k-rows x 16 x 16B
            int ch = t + i * 256;
            int kr = ch >> 4, cc = ch & 15;
            cpa16(sb + 18432 + kr * 272 + cc * 16, wop + (size_t)(kb + kr) * E_DIM + cc * 8);
        }
    };

    float acc[4][4][4];
#pragma unroll
    for (int mi = 0; mi < 4; mi++)
#pragma unroll
        for (int nt = 0; nt < 4; nt++)
#pragma unroll
            for (int q = 0; q < 4; q++) acc[mi][nt][q] = 0.f;

    int wm = w & 1, wn = w >> 1;
    int g = l >> 3, lr = l & 7;
    uint32_t a_off = ((g & 1) * 8 + lr) * 144 + (g >> 1) * 16;
    uint32_t b_off = ((g & 1) * 8 + lr) * 272 + (g >> 1) * 16;

    fill(0); CPA_COMMIT();
    fill(1); CPA_COMMIT();
    const int NC = KP2 / KC;  // 43
    for (int c = 0; c < NC; c++) {
        if (c + 1 < NC) cpa_wait<1>(); else cpa_wait<0>();
        __syncthreads();
        if (c + 2 < NC) { fill(c + 2); CPA_COMMIT(); }
        uint32_t sb = st0 + (c % 3) * ST2;
        uint32_t aB = sb + wm * 64 * 144;
        uint32_t bB = sb + 18432 + wn * 64;
#pragma unroll
        for (int ks = 0; ks < 4; ks++) {
            uint32_t af[4][4], bf[2][4];
#pragma unroll
            for (int mi = 0; mi < 4; mi++)
                LDM4(af[mi], aB + mi * 16 * 144 + ks * 32 + a_off);
            LDM4T(bf[0], bB + ks * 16 * 272 + b_off);
            LDM4T(bf[1], bB + ks * 16 * 272 + 32 + b_off);
#pragma unroll
            for (int mi = 0; mi < 4; mi++) {
                mma16(acc[mi][0], af[mi], bf[0][0], bf[0][1]);
                mma16(acc[mi][1], af[mi], bf[0][2], bf[0][3]);
                mma16(acc[mi][2], af[mi], bf[1][0], bf[1][1]);
                mma16(acc[mi][3], af[mi], bf[1][2], bf[1][3]);
            }
        }
    }

    const float* boB = bo + (size_t)e * E_DIM;
#pragma unroll
    for (int mi = 0; mi < 4; mi++)
#pragma unroll
        for (int nt = 0; nt < 4; nt++) {
            int r0 = wm * 64 + mi * 16 + (l >> 2);
            int c0 = cbase + wn * 32 + nt * 8 + (l & 3) * 2;
#pragma unroll
            for (int h8 = 0; h8 < 2; h8++) {
                int slot = rbase + r0 + h8 * 8;
                if (slot < rend) {
                    int tok = g_tok[slot];
                    float ww = g_wt[slot];
                    float* dst = g_acc + (size_t)tok * E_DIM;
                    atomicAdd(&dst[c0],     ww * (acc[mi][nt][h8 * 2]     + boB[c0]));
                    atomicAdd(&dst[c0 + 1], ww * (acc[mi][nt][h8 * 2 + 1] + boB[c0 + 1]));
                }
            }
        }
}

// ---------------- LayerNorm ----------------
__global__ void k_ln(const float* __restrict__ lng, const float* __restrict__ lnb,
                     float* __restrict__ out)
{
    int n = blockIdx.x, tid = threadIdx.x;
    const float4* row = (const float4*)(g_acc + (size_t)n * E_DIM);
    float4 v = row[tid];
    float s  = v.x + v.y + v.z + v.w;
    float ss = v.x * v.x + v.y * v.y + v.z * v.z + v.w * v.w;
#pragma unroll
    for (int o = 16; o > 0; o >>= 1) {
        s  += __shfl_xor_sync(0xffffffffu, s,  o);
        ss += __shfl_xor_sync(0xffffffffu, ss, o);
    }
    __shared__ float sred[16];
    int w = tid >> 5, l = tid & 31;
    if (l == 0) { sred[w] = s; sred[8 + w] = ss; }
    __syncthreads();
    if (tid < 32) {
        float a = (tid < 8) ? sred[tid] : 0.f;
        float c = (tid < 8) ? sred[8 + tid] : 0.f;
#pragma unroll
        for (int o = 4; o > 0; o >>= 1) {
            a += __shfl_xor_sync(0xffffffffu, a, o);
            c += __shfl_xor_sync(0xffffffffu, c, o);
        }
        if (tid == 0) { sred[0] = a; sred[1] = c; }
    }
    __syncthreads();
    float mu  = sred[0] * (1.f / E_DIM);
    float var = sred[1] * (1.f / E_DIM) - mu * mu;
    float inv = rsqrtf(var + 1e-5f);
    float4 g4 = ((const float4*)lng)[tid];
    float4 b4 = ((const float4*)lnb)[tid];
    float4 o4;
    o4.x = (v.x - mu) * inv * g4.x + b4.x;
    o4.y = (v.y - mu) * inv * g4.y + b4.y;
    o4.z = (v.z - mu) * inv * g4.z + b4.z;
    o4.w = (v.w - mu) * inv * g4.w + b4.w;
    ((float4*)out)[(size_t)n * (E_DIM / 4) + tid] = o4;
}

// ---------------- launcher ----------------
extern "C" void kernel_launch(void* const* d_in, const int* in_sizes, int n_in,
                              void* d_out, int out_size)
{
    const float* x   = (const float*)d_in[0];
    const float* Wr  = (const float*)d_in[1];
    const float* Wv  = (const float*)d_in[2];
    const float* bv  = (const float*)d_in[3];
    const float* Wg  = (const float*)d_in[4];
    const float* bg  = (const float*)d_in[5];
    const float* Wo  = (const float*)d_in[6];
    const float* bo  = (const float*)d_in[7];
    const float* lng = (const float*)d_in[8];
    const float* lnb = (const float*)d_in[9];
    float* out = (float*)d_out;

    cudaFuncSetAttribute(k_gemm1, cudaFuncAttributeMaxDynamicSharedMemorySize, SM1);
    cudaFuncSetAttribute(k_gemm2, cudaFuncAttributeMaxDynamicSharedMemorySize, SM2);

    {
        size_t pvg = (size_t)NEXP * E_DIM * (HPH / 2);
        k_cvt_vg<<<(unsigned)((pvg + 255) / 256), 256>>>(Wv, Wg);
        size_t po = (size_t)NEXP * KP2 * (E_DIM / 2);
        k_cvt_o<<<(unsigned)((po + 255) / 256), 256>>>(Wo);
    }
    k_init<<<(N_TOK * E_DIM / 4) / 256, 256>>>(x);
    k_router<<<(N_TOK * 32) / 256, 256>>>(x, Wr);
    k_scatter_one<<<1, 1024>>>();

    dim3 g1(MAXT, 43);
    k_gemm1<<<g1, 256, SM1>>>(bv, bg);

    dim3 g2(MAXT, 8);
    k_gemm2<<<g2, 256, SM2>>>(bo);

    k_ln<<<N_TOK, 256>>>(lng, lnb, out);
}

// round 8
// speedup vs baseline: 1.0539x; 1.0539x over previous
#include <cuda_runtime.h>
#include <cuda_fp16.h>
#include <math.h>
#include <stdint.h>

#define N_TOK 4096
#define E_DIM 1024
#define H_DIM 2730
#define HPH   2736          // fp16 weight row pad (×2B = 5472, 16B-aligned)
#define HP2   2752          // g_h fp16 row pad / GEMM2 K extent (43*64)
#define KP2   2752
#define NEXP  8
#define NPAIR 8192
#define MAXT  71            // 8192/128 + 7
#define KC    64

// ---------------- device scratch ----------------
__device__ int   g_cnt[NEXP];
__device__ int   g_off[NEXP + 1];
__device__ int   g_cur[NEXP];
__device__ int   g_te[N_TOK * 2];
__device__ float g_tw[N_TOK * 2];
__device__ int   g_tok[NPAIR];
__device__ float g_wt[NPAIR];
__device__ int   g_tile_e[MAXT];
__device__ int   g_tile_r[MAXT];
__device__ int   g_ntiles;
__device__ __align__(16) __half d_wvh[(size_t)NEXP * E_DIM * HPH + 64];
__device__ __align__(16) __half d_wgh[(size_t)NEXP * E_DIM * HPH + 64];
__device__ __align__(16) __half d_woh[(size_t)NEXP * KP2 * E_DIM];
__device__ __align__(16) __half d_xh[(size_t)N_TOK * E_DIM];
__device__ __align__(16) __half d_gh[(size_t)NPAIR * HP2];
__device__ __align__(16) float  g_acc[(size_t)N_TOK * E_DIM];

// ---------------- PTX helpers ----------------
__device__ __forceinline__ uint32_t smem_u32(const void* p) {
    uint32_t a;
    asm("{ .reg .u64 t; cvta.to.shared.u64 t, %1; cvt.u32.u64 %0, t; }" : "=r"(a) : "l"(p));
    return a;
}
__device__ __forceinline__ void cpa16(uint32_t dst, const void* src) {
    asm volatile("cp.async.cg.shared.global [%0], [%1], 16;" :: "r"(dst), "l"(src) : "memory");
}
#define CPA_COMMIT() asm volatile("cp.async.commit_group;" ::: "memory")
#define CPA_WAIT0()  asm volatile("cp.async.wait_group 0;" ::: "memory")
#define LDM4(r, a)                                                              \
    asm volatile("ldmatrix.sync.aligned.m8n8.x4.shared.b16 {%0,%1,%2,%3}, [%4];" \
        : "=r"((r)[0]), "=r"((r)[1]), "=r"((r)[2]), "=r"((r)[3]) : "r"(a))
#define LDM4T(r, a)                                                             \
    asm volatile("ldmatrix.sync.aligned.m8n8.x4.trans.shared.b16 {%0,%1,%2,%3}, [%4];" \
        : "=r"((r)[0]), "=r"((r)[1]), "=r"((r)[2]), "=r"((r)[3]) : "r"(a))

__device__ __forceinline__ void mma16(float d[4], const uint32_t a[4], uint32_t b0, uint32_t b1) {
    asm volatile(
        "mma.sync.aligned.m16n8k16.row.col.f32.f16.f16.f32 "
        "{%0,%1,%2,%3}, {%4,%5,%6,%7}, {%8,%9}, {%0,%1,%2,%3};"
        : "+f"(d[0]), "+f"(d[1]), "+f"(d[2]), "+f"(d[3])
        : "r"(a[0]), "r"(a[1]), "r"(a[2]), "r"(a[3]), "r"(b0), "r"(b1));
}

// ---------------- weight conversion (merged) ----------------
__global__ void k_cvt(const float* __restrict__ Wv, const float* __restrict__ Wg,
                      const float* __restrict__ Wo) {
    size_t p = (size_t)blockIdx.x * blockDim.x + threadIdx.x;
    if (p < (size_t)NEXP * E_DIM * (HPH / 2)) {
        int n2 = (int)(p % (HPH / 2));
        size_t r = p / (HPH / 2);
        int n = n2 * 2;
        size_t src = r * H_DIM + n;
        float v0 = (n     < H_DIM) ? Wv[src]     : 0.f;
        float v1 = (n + 1 < H_DIM) ? Wv[src + 1] : 0.f;
        float q0 = (n     < H_DIM) ? Wg[src]     : 0.f;
        float q1 = (n + 1 < H_DIM) ? Wg[src + 1] : 0.f;
        ((__half2*)d_wvh)[r * (HPH / 2) + n2] = __floats2half2_rn(v0, v1);
        ((__half2*)d_wgh)[r * (HPH / 2) + n2] = __floats2half2_rn(q0, q1);
    }
    if (p < (size_t)NEXP * KP2 * (E_DIM / 2)) {
        int n2 = (int)(p & (E_DIM / 2 - 1));
        size_t r = p >> 9;
        int k = (int)(r % KP2);
        int e = (int)(r / KP2);
        int n = n2 * 2;
        float v0 = 0.f, v1 = 0.f;
        if (k < H_DIM) {
            size_t src = ((size_t)e * H_DIM + k) * E_DIM + n;
            v0 = Wo[src]; v1 = Wo[src + 1];
        }
        ((__half2*)d_woh)[r * (E_DIM / 2) + n2] = __floats2half2_rn(v0, v1);
    }
}

// ---------------- init + router (merged; 1 block = 1 token) ----------------
__global__ void __launch_bounds__(256) k_init_router(
    const float* __restrict__ x, const float* __restrict__ Wr)
{
    int n = blockIdx.x, t = threadIdx.x;
    int w = t >> 5, l = t & 31;
    if (n == 0 && t < NEXP) g_cnt[t] = 0;

    __shared__ __align__(16) float4 sx[256];
    __shared__ float sacc[NEXP];

    float4 v = ((const float4*)x)[(size_t)n * 256 + t];
    sx[t] = v;
    ((float4*)g_acc)[(size_t)n * 256 + t] = v;
    ((__half2*)d_xh)[2 * ((size_t)n * 256 + t)]     = __floats2half2_rn(v.x, v.y);
    ((__half2*)d_xh)[2 * ((size_t)n * 256 + t) + 1] = __floats2half2_rn(v.z, v.w);
    __syncthreads();

    // warp w computes logit for expert w
    const float4* wr4 = (const float4*)(Wr + w * E_DIM);
    float acc = 0.f;
#pragma unroll
    for (int i = 0; i < 8; i++) {
        int k4 = i * 32 + l;
        float4 xv = sx[k4];
        float4 wv = wr4[k4];
        acc += xv.x * wv.x + xv.y * wv.y + xv.z * wv.z + xv.w * wv.w;
    }
#pragma unroll
    for (int o = 16; o > 0; o >>= 1) acc += __shfl_xor_sync(0xffffffffu, acc, o);
    if (l == 0) sacc[w] = acc;
    __syncthreads();

    if (t == 0) {
        int b0 = 0; float v0 = sacc[0];
#pragma unroll
        for (int c = 1; c < NEXP; c++) if (sacc[c] > v0) { v0 = sacc[c]; b0 = c; }
        int b1 = -1; float v1 = -3.4e38f;
#pragma unroll
        for (int c = 0; c < NEXP; c++) if (c != b0 && sacc[c] > v1) { v1 = sacc[c]; b1 = c; }
        float tt = expf(v1 - v0);
        float w0 = 1.f / (1.f + tt);
        g_te[n * 2 + 0] = b0; g_tw[n * 2 + 0] = w0;
        g_te[n * 2 + 1] = b1; g_tw[n * 2 + 1] = tt * w0;
        atomicAdd(&g_cnt[b0], 1);
        atomicAdd(&g_cnt[b1], 1);
    }
}

// ---------------- prefix + scatter ----------------
__global__ void k_scatter_one() {
    int t = threadIdx.x;
    if (t == 0) {
        int s = 0;
        for (int c = 0; c < NEXP; c++) { g_off[c] = s; g_cur[c] = s; s += g_cnt[c]; }
        g_off[NEXP] = s;
        int tt = 0;
        for (int c = 0; c < NEXP; c++)
            for (int r = g_off[c]; r < g_off[c + 1]; r += 128) {
                g_tile_e[tt] = c; g_tile_r[tt] = r; tt++;
            }
        g_ntiles = tt;
    }
    __syncthreads();
    for (int n = t; n < N_TOK; n += blockDim.x) {
#pragma unroll
        for (int k = 0; k < 2; k++) {
            int e = g_te[n * 2 + k];
            int slot = atomicAdd(&g_cur[e], 1);
            g_tok[slot] = n;
            g_wt[slot]  = g_tw[n * 2 + k];
        }
    }
}

// ============ GEMM1: fp16 mma, h = silu(X@Wv+bv)*(X@Wg+bg) ============
// CTA 128 tok x 64 H-cols; warps 0-3 -> V, 4-7 -> G (shared A).
// warp tile 64 tok x 32 cols. 2-stage cp.async pipeline.
#define ST1   36864
#define SM1   (512 + 2 * ST1)
#define ST2   (18432 + 17408)
#define SM2   (2 * ST2)

__global__ void __launch_bounds__(256, 2) k_gemm1(
    const float* __restrict__ bv, const float* __restrict__ bg)
{
    int tile = blockIdx.x;
    if (tile >= g_ntiles) return;
    int e = g_tile_e[tile];
    int rbase = g_tile_r[tile];
    int rend  = g_off[e + 1];
    int cbase = blockIdx.y * 64;

    extern __shared__ __align__(16) char dsm[];
    int* stok = (int*)dsm;
    uint32_t st0 = smem_u32(dsm + 512);
    int t = threadIdx.x, w = t >> 5, l = t & 31;

    if (t < 128) {
        int s = rbase + t;
        stok[t] = g_tok[s < rend ? s : rend - 1];
    }
    __syncthreads();

    const __half* wvp = d_wvh + ((size_t)e * E_DIM) * HPH + cbase;
    const __half* wgp = d_wgh + ((size_t)e * E_DIM) * HPH + cbase;

    auto fill = [&](int c) {
        uint32_t sb = st0 + (c & 1) * ST1;
        int kb = c * KC;
#pragma unroll
        for (int i = 0; i < 4; i++) {          // A: 128 rows x 8 x 16B
            int ch = t + i * 256;
            int row = ch >> 3, cc = ch & 7;
            cpa16(sb + row * 144 + cc * 16, d_xh + (size_t)stok[row] * E_DIM + kb + cc * 8);
        }
#pragma unroll
        for (int i = 0; i < 2; i++) {          // Bv,Bg: 64 k-rows x 8 x 16B each
            int ch = t + i * 256;
            int kr = ch >> 3, cc = ch & 7;
            uint32_t off = kr * 144 + cc * 16;
            cpa16(sb + 18432 + off, wvp + (size_t)(kb + kr) * HPH + cc * 8);
            cpa16(sb + 27648 + off, wgp + (size_t)(kb + kr) * HPH + cc * 8);
        }
    };

    float acc[4][4][4];
#pragma unroll
    for (int mi = 0; mi < 4; mi++)
#pragma unroll
        for (int nt = 0; nt < 4; nt++)
#pragma unroll
            for (int q = 0; q < 4; q++) acc[mi][nt][q] = 0.f;

    int wl = w & 3;
    int wm = wl & 1, wn = wl >> 1;
    bool isG = (w >= 4);
    int g = l >> 3, lr = l & 7;
    uint32_t frag_off = ((g & 1) * 8 + lr) * 144 + (g >> 1) * 16;

    fill(0); CPA_COMMIT();
    for (int c = 0; c < 16; c++) {
        CPA_WAIT0();
        __syncthreads();
        if (c + 1 < 16) { fill(c + 1); CPA_COMMIT(); }
        uint32_t sb = st0 + (c & 1) * ST1;
        uint32_t aB = sb + wm * 64 * 144;
        uint32_t bB = sb + (isG ? 27648u : 18432u) + wn * 64;
#pragma unroll
        for (int ks = 0; ks < 4; ks++) {
            uint32_t af[4][4], bf[2][4];
#pragma unroll
            for (int mi = 0; mi < 4; mi++)
                LDM4(af[mi], aB + mi * 16 * 144 + ks * 32 + frag_off);
            LDM4T(bf[0], bB + ks * 16 * 144 + frag_off);
            LDM4T(bf[1], bB + ks * 16 * 144 + 32 + frag_off);
#pragma unroll
            for (int mi = 0; mi < 4; mi++) {
                mma16(acc[mi][0], af[mi], bf[0][0], bf[0][1]);
                mma16(acc[mi][1], af[mi], bf[0][2], bf[0][3]);
                mma16(acc[mi][2], af[mi], bf[1][0], bf[1][1]);
                mma16(acc[mi][3], af[mi], bf[1][2], bf[1][3]);
            }
        }
    }

    // epilogue: V warps stage to sV (overlay stage buffers); G warps fuse SwiGLU
    __syncthreads();
    float* sV = (float*)(dsm + 512);
    if (!isG) {
#pragma unroll
        for (int mi = 0; mi < 4; mi++)
#pragma unroll
            for (int nt = 0; nt < 4; nt++) {
                int r0 = wm * 64 + mi * 16 + (l >> 2);
                int c0 = wn * 32 + nt * 8 + (l & 3) * 2;
                *(float2*)&sV[r0 * 66 + c0]       = make_float2(acc[mi][nt][0], acc[mi][nt][1]);
                *(float2*)&sV[(r0 + 8) * 66 + c0] = make_float2(acc[mi][nt][2], acc[mi][nt][3]);
            }
    }
    __syncthreads();
    if (isG) {
        const float* bvB = bv + (size_t)e * H_DIM;
        const float* bgB = bg + (size_t)e * H_DIM;
#pragma unroll
        for (int mi = 0; mi < 4; mi++)
#pragma unroll
            for (int nt = 0; nt < 4; nt++) {
                int r0 = wm * 64 + mi * 16 + (l >> 2);
                int c0 = wn * 32 + nt * 8 + (l & 3) * 2;
#pragma unroll
                for (int h8 = 0; h8 < 2; h8++) {
                    int row = r0 + h8 * 8;
                    int slot = rbase + row;
                    if (slot < rend) {
                        float2 vv = *(float2*)&sV[row * 66 + c0];
                        int gc = cbase + c0;
                        float o0 = 0.f, o1 = 0.f;
                        if (gc < H_DIM) {
                            float a = vv.x + bvB[gc];
                            float gg = acc[mi][nt][h8 * 2] + bgB[gc];
                            o0 = a / (1.f + __expf(-a)) * gg;
                        }
                        if (gc + 1 < H_DIM) {
                            float a = vv.y + bvB[gc + 1];
                            float gg = acc[mi][nt][h8 * 2 + 1] + bgB[gc + 1];
                            o1 = a / (1.f + __expf(-a)) * gg;
                        }
                        *(__half2*)&d_gh[(size_t)slot * HP2 + gc] = __floats2half2_rn(o0, o1);
                    }
                }
            }
    }
}

// ============ GEMM2: acc += w * (h @ Wo + bo), fp16 mma ============
// CTA 128 tok x 128 E-cols; warps 2(M) x 4(N), warp tile 64x32. 2-stage.
__global__ void __launch_bounds__(256, 2) k_gemm2(const float* __restrict__ bo)
{
    int tile = blockIdx.x;
    if (tile >= g_ntiles) return;
    int e = g_tile_e[tile];
    int rbase = g_tile_r[tile];
    int rend  = g_off[e + 1];
    int cbase = blockIdx.y * 128;

    extern __shared__ __align__(16) char dsm[];
    uint32_t st0 = smem_u32(dsm);
    int t = threadIdx.x, w = t >> 5, l = t & 31;

    const __half* wop = d_woh + (size_t)e * KP2 * E_DIM + cbase;

    auto fill = [&](int c) {
        uint32_t sb = st0 + (c & 1) * ST2;
        int kb = c * KC;
#pragma unroll
        for (int i = 0; i < 4; i++) {          // A: 128 rows x 8 x 16B
            int ch = t + i * 256;
            int row = ch >> 3, cc = ch & 7;
            int slot = rbase + row; if (slot >= rend) slot = rend - 1;
            cpa16(sb + row * 144 + cc * 16, d_gh + (size_t)slot * HP2 + kb + cc * 8);
        }
#pragma unroll
        for (int i = 0; i < 4; i++) {          // B: 64 k-rows x 16 x 16B
            int ch = t + i * 256;
            int kr = ch >> 4, cc = ch & 15;
            cpa16(sb + 18432 + kr * 272 + cc * 16, wop + (size_t)(kb + kr) * E_DIM + cc * 8);
        }
    };

    float acc[4][4][4];
#pragma unroll
    for (int mi = 0; mi < 4; mi++)
#pragma unroll
        for (int nt = 0; nt < 4; nt++)
#pragma unroll
            for (int q = 0; q < 4; q++) acc[mi][nt][q] = 0.f;

    int wm = w & 1, wn = w >> 1;
    int g = l >> 3, lr = l & 7;
    uint32_t a_off = ((g & 1) * 8 + lr) * 144 + (g >> 1) * 16;
    uint32_t b_off = ((g & 1) * 8 + lr) * 272 + (g >> 1) * 16;

    fill(0); CPA_COMMIT();
    const int NC = KP2 / KC;  // 43
    for (int c = 0; c < NC; c++) {
        CPA_WAIT0();
        __syncthreads();
        if (c + 1 < NC) { fill(c + 1); CPA_COMMIT(); }
        uint32_t sb = st0 + (c & 1) * ST2;
        uint32_t aB = sb + wm * 64 * 144;
        uint32_t bB = sb + 18432 + wn * 64;
#pragma unroll
        for (int ks = 0; ks < 4; ks++) {
            uint32_t af[4][4], bf[2][4];
#pragma unroll
            for (int mi = 0; mi < 4; mi++)
                LDM4(af[mi], aB + mi * 16 * 144 + ks * 32 + a_off);
            LDM4T(bf[0], bB + ks * 16 * 272 + b_off);
            LDM4T(bf[1], bB + ks * 16 * 272 + 32 + b_off);
#pragma unroll
            for (int mi = 0; mi < 4; mi++) {
                mma16(acc[mi][0], af[mi], bf[0][0], bf[0][1]);
                mma16(acc[mi][1], af[mi], bf[0][2], bf[0][3]);
                mma16(acc[mi][2], af[mi], bf[1][0], bf[1][1]);
                mma16(acc[mi][3], af[mi], bf[1][2], bf[1][3]);
            }
        }
    }

    const float* boB = bo + (size_t)e * E_DIM;
#pragma unroll
    for (int mi = 0; mi < 4; mi++)
#pragma unroll
        for (int nt = 0; nt < 4; nt++) {
            int r0 = wm * 64 + mi * 16 + (l >> 2);
            int c0 = cbase + wn * 32 + nt * 8 + (l & 3) * 2;
#pragma unroll
            for (int h8 = 0; h8 < 2; h8++) {
                int slot = rbase + r0 + h8 * 8;
                if (slot < rend) {
                    int tok = g_tok[slot];
                    float ww = g_wt[slot];
                    float* dst = g_acc + (size_t)tok * E_DIM;
                    atomicAdd(&dst[c0],     ww * (acc[mi][nt][h8 * 2]     + boB[c0]));
                    atomicAdd(&dst[c0 + 1], ww * (acc[mi][nt][h8 * 2 + 1] + boB[c0 + 1]));
                }
            }
        }
}

// ---------------- LayerNorm ----------------
__global__ void k_ln(const float* __restrict__ lng, const float* __restrict__ lnb,
                     float* __restrict__ out)
{
    int n = blockIdx.x, tid = threadIdx.x;
    const float4* row = (const float4*)(g_acc + (size_t)n * E_DIM);
    float4 v = row[tid];
    float s  = v.x + v.y + v.z + v.w;
    float ss = v.x * v.x + v.y * v.y + v.z * v.z + v.w * v.w;
#pragma unroll
    for (int o = 16; o > 0; o >>= 1) {
        s  += __shfl_xor_sync(0xffffffffu, s,  o);
        ss += __shfl_xor_sync(0xffffffffu, ss, o);
    }
    __shared__ float sred[16];
    int w = tid >> 5, l = tid & 31;
    if (l == 0) { sred[w] = s; sred[8 + w] = ss; }
    __syncthreads();
    if (tid < 32) {
        float a = (tid < 8) ? sred[tid] : 0.f;
        float c = (tid < 8) ? sred[8 + tid] : 0.f;
#pragma unroll
        for (int o = 4; o > 0; o >>= 1) {
            a += __shfl_xor_sync(0xffffffffu, a, o);
            c += __shfl_xor_sync(0xffffffffu, c, o);
        }
        if (tid == 0) { sred[0] = a; sred[1] = c; }
    }
    __syncthreads();
    float mu  = sred[0] * (1.f / E_DIM);
    float var = sred[1] * (1.f / E_DIM) - mu * mu;
    float inv = rsqrtf(var + 1e-5f);
    float4 g4 = ((const float4*)lng)[tid];
    float4 b4 = ((const float4*)lnb)[tid];
    float4 o4;
    o4.x = (v.x - mu) * inv * g4.x + b4.x;
    o4.y = (v.y - mu) * inv * g4.y + b4.y;
    o4.z = (v.z - mu) * inv * g4.z + b4.z;
    o4.w = (v.w - mu) * inv * g4.w + b4.w;
    ((float4*)out)[(size_t)n * (E_DIM / 4) + tid] = o4;
}

// ---------------- launcher ----------------
extern "C" void kernel_launch(void* const* d_in, const int* in_sizes, int n_in,
                              void* d_out, int out_size)
{
    const float* x   = (const float*)d_in[0];
    const float* Wr  = (const float*)d_in[1];
    const float* Wv  = (const float*)d_in[2];
    const float* bv  = (const float*)d_in[3];
    const float* Wg  = (const float*)d_in[4];
    const float* bg  = (const float*)d_in[5];
    const float* Wo  = (const float*)d_in[6];
    const float* bo  = (const float*)d_in[7];
    const float* lng = (const float*)d_in[8];
    const float* lnb = (const float*)d_in[9];
    float* out = (float*)d_out;

    cudaFuncSetAttribute(k_gemm1, cudaFuncAttributeMaxDynamicSharedMemorySize, SM1);
    cudaFuncSetAttribute(k_gemm2, cudaFuncAttributeMaxDynamicSharedMemorySize, SM2);

    size_t pmax = (size_t)NEXP * KP2 * (E_DIM / 2);   // > NEXP*E_DIM*(HPH/2)
    k_cvt<<<(unsigned)((pmax + 255) / 256), 256>>>(Wv, Wg, Wo);   // 0
    k_init_router<<<N_TOK, 256>>>(x, Wr);                         // 1
    k_scatter_one<<<1, 1024>>>();                                 // 2

    dim3 g1(MAXT, 43);
    k_gemm1<<<g1, 256, SM1>>>(bv, bg);                            // 3 <- profiled slot

    dim3 g2(MAXT, 8);
    k_gemm2<<<g2, 256, SM2>>>(bo);                                // 4

    k_ln<<<N_TOK, 256>>>(lng, lnb, out);                          // 5
}